// round 14
// baseline (speedup 1.0000x reference)
#include <cuda_runtime.h>
#include <cuda_fp16.h>
#include <cstdint>

// CrystalLinear: Y = X @ W^T + bias (fp16 tensors served as f32 upcasts).
// mma.sync path (harness ptxas = sm_103; tcgen05 unavailable).
// R14: 3-stage ring, single barrier per k-tile. A: cp.async 2 ahead (fp16
// scratch). B: packed LDG 2 ahead -> held in regs -> decode+STS 1 ahead
// (off critical path). No decoded-W scratch pass.

namespace {
constexpr int Mdim = 1024;
constexpr int Kdim = 8192;
constexpr int Ndim = 8192;
constexpr int KW   = Kdim / 16;   // 512

constexpr int BM = 128;
constexpr int BN = 128;
constexpr int BK = 64;            // 64 fp16 = 128B row
constexpr int KT = Kdim / BK;     // 128
constexpr int NTHREADS = 256;

constexpr int STAGE_BYTES = (BM + BN) * 128;     // 32 KB (A then B)
constexpr int SMEM_TOTAL  = 3 * STAGE_BYTES;     // 96 KB -> 2 CTAs/SM

constexpr uint32_t F16_LUT = 0x42403C00u;  // codes 0..3 -> fp16 0,1,2,3 hi-bytes
}

__host__ __device__ constexpr int offA(int s) { return s * STAGE_BYTES; }
__host__ __device__ constexpr int offB(int s) { return s * STAGE_BYTES + BM * 128; }

__device__ __half g_Xh[(size_t)Mdim * Kdim];   // 16 MB fp16 X

// ---------------- helpers ----------------
__device__ __forceinline__ uint32_t smem_u32(const void* p) {
    uint32_t a;
    asm("{ .reg .u64 t; cvta.to.shared.u64 t, %1; cvt.u32.u64 %0, t; }"
        : "=r"(a) : "l"(p));
    return a;
}
__device__ __forceinline__ uint32_t pack_f16x2(float lo, float hi) {
    uint32_t l = (uint32_t)__half_as_ushort(__float2half_rn(lo));
    uint32_t h = (uint32_t)__half_as_ushort(__float2half_rn(hi));
    return l | (h << 16);
}
__device__ __forceinline__ void decode_word(uint32_t w, uint32_t* dst8) {
#pragma unroll
    for (int j = 0; j < 8; ++j) {
        uint32_t bits = (w >> (4 * j)) & 0xFu;
        uint32_t sel  = ((bits & 3u) << 4) | ((bits & 0xCu) << 10);
        dst8[j] = __byte_perm(F16_LUT, F16_LUT, sel);
    }
}
__device__ __forceinline__ void cp_async16(uint32_t dst, const void* src) {
    asm volatile("cp.async.cg.shared.global [%0], [%1], 16;"
                 :: "r"(dst), "l"(src) : "memory");
}
__device__ __forceinline__ void cp_commit() {
    asm volatile("cp.async.commit_group;" ::: "memory");
}
__device__ __forceinline__ void cp_wait0() {
    asm volatile("cp.async.wait_group 0;" ::: "memory");
}
__device__ __forceinline__ void cp_wait1() {
    asm volatile("cp.async.wait_group 1;" ::: "memory");
}
__device__ __forceinline__ void ldsm4(uint32_t* r, uint32_t a) {
    asm volatile("ldmatrix.sync.aligned.m8n8.x4.shared.b16 {%0,%1,%2,%3}, [%4];"
                 : "=r"(r[0]), "=r"(r[1]), "=r"(r[2]), "=r"(r[3]) : "r"(a));
}
__device__ __forceinline__ void mma_f16(float c[4], const uint32_t a[4],
                                        const uint32_t b0, const uint32_t b1) {
    asm volatile(
        "mma.sync.aligned.m16n8k16.row.col.f32.f16.f16.f32 "
        "{%0,%1,%2,%3}, {%4,%5,%6,%7}, {%8,%9}, {%0,%1,%2,%3};\n"
        : "+f"(c[0]), "+f"(c[1]), "+f"(c[2]), "+f"(c[3])
        : "r"(a[0]), "r"(a[1]), "r"(a[2]), "r"(a[3]), "r"(b0), "r"(b1));
}

// ---------------- pass 1: X f32 -> fp16 ----------------
__global__ __launch_bounds__(256) void convert_x_kernel(const float* __restrict__ X) {
    size_t i = ((size_t)blockIdx.x * 256 + threadIdx.x) * 4;
    float4 v = *reinterpret_cast<const float4*>(X + i);
    uint2 h;
    h.x = pack_f16x2(v.x, v.y);
    h.y = pack_f16x2(v.z, v.w);
    *reinterpret_cast<uint2*>(&g_Xh[i]) = h;
}

// ---------------- pass 2: GEMM ----------------
__global__ __launch_bounds__(NTHREADS, 2)
void ternary_gemm_kernel(const int*   __restrict__ Wp,
                         const float* __restrict__ bias,
                         float*       __restrict__ Y) {
    extern __shared__ char smem[];
    const uint32_t sbase = smem_u32(smem);

    const int tid    = threadIdx.x;
    const int lane   = tid & 31;
    const int wid    = tid >> 5;
    const int warp_m = wid >> 2;   // 0..1 (64 rows)
    const int warp_n = wid & 3;    // 0..3 (32 cols)
    const int n0     = blockIdx.x * BN;
    const int m0     = blockIdx.y * BM;

    // producer mappings
    const int prow = tid >> 3;     // A: 0..31 (+ i*32)
    const int pc   = tid & 7;      // A: 16B chunk in 128B row
    const int b_n  = tid >> 1;     // B: 0..127
    const int b_h  = tid & 1;      // B: which 64B half (32 k)

    // ldmatrix lane addressing
    const int lr = lane & 7;
    const int lg = lane >> 3;
    const int a_r  = warp_m * 64 + lr + (lg & 1) * 8;  // + mt*16
    const int a_cb = lg >> 1;
    const int b_r  = warp_n * 32 + lr + (lg >> 1) * 8; // + p*16
    const int b_cb = lg & 1;

    auto issueA = [&](int kt, int s) {
#pragma unroll
        for (int i = 0; i < 4; ++i) {
            const int row = prow + i * 32;
            const uint32_t sw = ((pc ^ (row & 7)) << 4);
            cp_async16(sbase + offA(s) + row * 128 + sw,
                       &g_Xh[(size_t)(m0 + row) * Kdim + kt * BK + pc * 8]);
        }
        cp_commit();
    };
    auto loadB = [&](int kt) {
        return *reinterpret_cast<const int2*>(
            &Wp[(size_t)(n0 + b_n) * KW + kt * 4 + b_h * 2]);
    };
    auto storeB = [&](int2 wv, int s) {
        uint32_t dec[16];
        decode_word((uint32_t)wv.x, dec);
        decode_word((uint32_t)wv.y, dec + 8);
        char* const pb = smem + offB(s) + b_n * 128;
        const int rx = b_n & 7;
#pragma unroll
        for (int g = 0; g < 4; ++g) {
            *reinterpret_cast<uint4*>(pb + (((b_h * 4 + g) ^ rx) << 4)) =
                make_uint4(dec[4 * g], dec[4 * g + 1], dec[4 * g + 2], dec[4 * g + 3]);
        }
    };

    float acc[4][4][4];
#pragma unroll
    for (int mt = 0; mt < 4; ++mt)
#pragma unroll
        for (int nt = 0; nt < 4; ++nt)
#pragma unroll
            for (int i = 0; i < 4; ++i) acc[mt][nt][i] = 0.0f;

    // prologue: B(0) decoded+stored now; B(1) held in regs; A stages 0,1 in flight
    storeB(loadB(0), 0);
    int2 bReg = loadB(1);
    issueA(0, 0);
    issueA(1, 1);

    int s = 0, s1 = 1, s2 = 2;   // current, +1 (B store target), +2 (A refill)
    for (int kt = 0; kt < KT; ++kt) {
        if (kt + 1 == KT) cp_wait0(); else cp_wait1();  // A(s) complete
        __syncthreads();   // stage s visible; old readers of s1/s2 are done

        if (kt + 1 < KT) storeB(bReg, s1);     // B for kt+1 (off critical path)
        if (kt + 2 < KT) {
            issueA(kt + 2, s2);                // A for kt+2
            bReg = loadB(kt + 2);              // packed B for kt+2 (latency slack)
        }

        const uint32_t aBase = sbase + offA(s);
        const uint32_t bBase = sbase + offB(s);
#pragma unroll
        for (int ks = 0; ks < 4; ++ks) {
            const int ks2 = ks * 2;
            uint32_t afr[4][4], bq[2][4];
#pragma unroll
            for (int mt = 0; mt < 4; ++mt)
                ldsm4(afr[mt], aBase + (a_r + mt * 16) * 128 +
                                   (((ks2 + a_cb) ^ lr) << 4));
#pragma unroll
            for (int p = 0; p < 2; ++p)
                ldsm4(bq[p], bBase + (b_r + p * 16) * 128 +
                                 (((ks2 + b_cb) ^ lr) << 4));
#pragma unroll
            for (int mt = 0; mt < 4; ++mt)
#pragma unroll
                for (int nt = 0; nt < 4; ++nt)
                    mma_f16(acc[mt][nt], afr[mt],
                            bq[nt >> 1][(nt & 1) * 2],
                            bq[nt >> 1][(nt & 1) * 2 + 1]);
        }
        // single-barrier ring (safety per header comment)
        s  = (s  == 2) ? 0 : s  + 1;
        s1 = (s1 == 2) ? 0 : s1 + 1;
        s2 = (s2 == 2) ? 0 : s2 + 1;
    }

    // epilogue: reference numerics f32( fp16(acc) +fp16 fp16(bias) )
#pragma unroll
    for (int mt = 0; mt < 4; ++mt) {
#pragma unroll
        for (int nt = 0; nt < 4; ++nt) {
            const int row = m0 + warp_m * 64 + mt * 16 + (lane >> 2);
            const int col = n0 + warp_n * 32 + nt * 8 + (lane & 3) * 2;
            const __half b0 = __float2half_rn(bias[col]);
            const __half b1 = __float2half_rn(bias[col + 1]);
#pragma unroll
            for (int h = 0; h < 2; ++h) {
                const __half s0 = __hadd(__float2half(acc[mt][nt][2 * h + 0]), b0);
                const __half s1h = __hadd(__float2half(acc[mt][nt][2 * h + 1]), b1);
                float2 o;
                o.x = __half2float(s0);
                o.y = __half2float(s1h);
                *reinterpret_cast<float2*>(
                    &Y[(size_t)(row + 8 * h) * Ndim + col]) = o;
            }
        }
    }
}

extern "C" void kernel_launch(void* const* d_in, const int* in_sizes, int n_in,
                              void* d_out, int out_size) {
    const float* x    = nullptr;
    const int*   wp   = nullptr;
    const float* bias = nullptr;
    for (int i = 0; i < n_in; ++i) {
        if (in_sizes[i] == Mdim * Kdim)      x    = (const float*)d_in[i];
        else if (in_sizes[i] == Ndim * KW)   wp   = (const int*)d_in[i];
        else if (in_sizes[i] == Ndim)        bias = (const float*)d_in[i];
    }
    float* y = (float*)d_out;

    cudaFuncSetAttribute(ternary_gemm_kernel,
                         cudaFuncAttributeMaxDynamicSharedMemorySize, SMEM_TOTAL);

    convert_x_kernel<<<(Mdim * Kdim) / (256 * 4), 256>>>(x);
    dim3 grid(Ndim / BN, Mdim / BM);   // (64, 8) = 512 CTAs
    ternary_gemm_kernel<<<grid, NTHREADS, SMEM_TOTAL>>>(wp, bias, y);
}

// round 16
// speedup vs baseline: 1.1141x; 1.1141x over previous
#include <cuda_runtime.h>
#include <cuda_fp16.h>
#include <cstdint>

// CrystalLinear: Y = X @ W^T + bias (fp16 tensors served as f32 upcasts).
// mma.sync path (harness ptxas = sm_103; tcgen05 unavailable).
// R15 = R13 (best): W pre-decoded to fp16 scratch, 3-stage cp.async ring,
// single barrier per k-tile, ldmatrix + XOR swizzle. Changes: fused
// convert_x+decode_w pre-pass (one launch), final-iter wait_group 0,
// float2 bias loads.

namespace {
constexpr int Mdim = 1024;
constexpr int Kdim = 8192;
constexpr int Ndim = 8192;
constexpr int KW   = Kdim / 16;   // 512

constexpr int BM = 128;
constexpr int BN = 128;
constexpr int BK = 64;            // 64 fp16 = 128B row
constexpr int KT = Kdim / BK;     // 128
constexpr int NTHREADS = 256;

constexpr int STAGE_BYTES = (BM + BN) * 128;     // 32 KB (A then B)
constexpr int SMEM_TOTAL  = 3 * STAGE_BYTES;     // 96 KB -> 2 CTAs/SM

constexpr int XCONV_BLOCKS = (Mdim * Kdim) / (256 * 4);   // 8192
constexpr int WDEC_BLOCKS  = (Ndim * KW) / 256;           // 16384

constexpr uint32_t F16_LUT = 0x42403C00u;  // codes 0..3 -> fp16 0,1,2,3 hi-bytes
}

__host__ __device__ constexpr int offA(int s) { return s * STAGE_BYTES; }
__host__ __device__ constexpr int offB(int s) { return s * STAGE_BYTES + BM * 128; }

__device__ __half g_Xh[(size_t)Mdim * Kdim];   // 16 MB fp16 X
__device__ __half g_Wh[(size_t)Ndim * Kdim];   // 128 MB fp16 decoded W

// ---------------- helpers ----------------
__device__ __forceinline__ uint32_t smem_u32(const void* p) {
    uint32_t a;
    asm("{ .reg .u64 t; cvta.to.shared.u64 t, %1; cvt.u32.u64 %0, t; }"
        : "=r"(a) : "l"(p));
    return a;
}
__device__ __forceinline__ uint32_t pack_f16x2(float lo, float hi) {
    uint32_t l = (uint32_t)__half_as_ushort(__float2half_rn(lo));
    uint32_t h = (uint32_t)__half_as_ushort(__float2half_rn(hi));
    return l | (h << 16);
}
__device__ __forceinline__ void decode_word(uint32_t w, uint32_t* dst8) {
#pragma unroll
    for (int j = 0; j < 8; ++j) {
        uint32_t bits = (w >> (4 * j)) & 0xFu;
        uint32_t sel  = ((bits & 3u) << 4) | ((bits & 0xCu) << 10);
        dst8[j] = __byte_perm(F16_LUT, F16_LUT, sel);
    }
}
__device__ __forceinline__ void cp_async16(uint32_t dst, const void* src) {
    asm volatile("cp.async.cg.shared.global [%0], [%1], 16;"
                 :: "r"(dst), "l"(src) : "memory");
}
__device__ __forceinline__ void cp_commit() {
    asm volatile("cp.async.commit_group;" ::: "memory");
}
__device__ __forceinline__ void cp_wait0() {
    asm volatile("cp.async.wait_group 0;" ::: "memory");
}
__device__ __forceinline__ void cp_wait1() {
    asm volatile("cp.async.wait_group 1;" ::: "memory");
}
__device__ __forceinline__ void ldsm4(uint32_t* r, uint32_t a) {
    asm volatile("ldmatrix.sync.aligned.m8n8.x4.shared.b16 {%0,%1,%2,%3}, [%4];"
                 : "=r"(r[0]), "=r"(r[1]), "=r"(r[2]), "=r"(r[3]) : "r"(a));
}
__device__ __forceinline__ void mma_f16(float c[4], const uint32_t a[4],
                                        const uint32_t b0, const uint32_t b1) {
    asm volatile(
        "mma.sync.aligned.m16n8k16.row.col.f32.f16.f16.f32 "
        "{%0,%1,%2,%3}, {%4,%5,%6,%7}, {%8,%9}, {%0,%1,%2,%3};\n"
        : "+f"(c[0]), "+f"(c[1]), "+f"(c[2]), "+f"(c[3])
        : "r"(a[0]), "r"(a[1]), "r"(a[2]), "r"(a[3]), "r"(b0), "r"(b1));
}

// ---------------- pass 1 (fused): X f32->fp16 AND packed W -> fp16 ----------
__global__ __launch_bounds__(256)
void prepare_kernel(const float* __restrict__ X, const int* __restrict__ Wp) {
    if (blockIdx.x < XCONV_BLOCKS) {
        size_t i = ((size_t)blockIdx.x * 256 + threadIdx.x) * 4;
        float4 v = *reinterpret_cast<const float4*>(X + i);
        uint2 h;
        h.x = pack_f16x2(v.x, v.y);
        h.y = pack_f16x2(v.z, v.w);
        *reinterpret_cast<uint2*>(&g_Xh[i]) = h;
    } else {
        size_t wi = ((size_t)(blockIdx.x - XCONV_BLOCKS)) * 256 + threadIdx.x;
        uint32_t w = (uint32_t)Wp[wi];
        uint32_t dec[8];
        decode_word(w, dec);
        uint4* dst = reinterpret_cast<uint4*>(&g_Wh[wi * 16]);
        dst[0] = make_uint4(dec[0], dec[1], dec[2], dec[3]);
        dst[1] = make_uint4(dec[4], dec[5], dec[6], dec[7]);
    }
}

// ---------------- pass 2: GEMM ----------------
__global__ __launch_bounds__(NTHREADS, 2)
void ternary_gemm_kernel(const float* __restrict__ bias,
                         float*       __restrict__ Y) {
    extern __shared__ char smem[];
    const uint32_t sbase = smem_u32(smem);

    const int tid    = threadIdx.x;
    const int lane   = tid & 31;
    const int wid    = tid >> 5;
    const int warp_m = wid >> 2;   // 0..1 (64 rows)
    const int warp_n = wid & 3;    // 0..3 (32 cols)
    const int n0     = blockIdx.x * BN;
    const int m0     = blockIdx.y * BM;

    // producer mapping (same for A and B tiles)
    const int prow = tid >> 3;     // 0..31 (+ i*32)
    const int pc   = tid & 7;      // 16B chunk in 128B row

    // ldmatrix lane addressing
    const int lr = lane & 7;
    const int lg = lane >> 3;
    const int a_r  = warp_m * 64 + lr + (lg & 1) * 8;  // + mt*16
    const int a_cb = lg >> 1;
    const int b_r  = warp_n * 32 + lr + (lg >> 1) * 8; // + p*16
    const int b_cb = lg & 1;

    auto issueStage = [&](int kt, int s) {
#pragma unroll
        for (int i = 0; i < 4; ++i) {
            const int row = prow + i * 32;
            const uint32_t sw = ((pc ^ (row & 7)) << 4);
            cp_async16(sbase + offA(s) + row * 128 + sw,
                       &g_Xh[(size_t)(m0 + row) * Kdim + kt * BK + pc * 8]);
            cp_async16(sbase + offB(s) + row * 128 + sw,
                       &g_Wh[(size_t)(n0 + row) * Kdim + kt * BK + pc * 8]);
        }
        cp_commit();
    };

    float acc[4][4][4];
#pragma unroll
    for (int mt = 0; mt < 4; ++mt)
#pragma unroll
        for (int nt = 0; nt < 4; ++nt)
#pragma unroll
            for (int i = 0; i < 4; ++i) acc[mt][nt][i] = 0.0f;

    // prologue: stages 0 and 1 in flight
    issueStage(0, 0);
    issueStage(1, 1);

    int s = 0, s2 = 2;   // current stage, refill target (kt+2)
    for (int kt = 0; kt < KT; ++kt) {
        if (kt + 1 == KT) cp_wait0(); else cp_wait1();  // stage s complete
        __syncthreads();   // stage s visible; prior readers of s2 are done

        if (kt + 2 < KT) issueStage(kt + 2, s2);

        const uint32_t aBase = sbase + offA(s);
        const uint32_t bBase = sbase + offB(s);
#pragma unroll
        for (int ks = 0; ks < 4; ++ks) {
            const int ks2 = ks * 2;
            uint32_t afr[4][4], bq[2][4];
#pragma unroll
            for (int mt = 0; mt < 4; ++mt)
                ldsm4(afr[mt], aBase + (a_r + mt * 16) * 128 +
                                   (((ks2 + a_cb) ^ lr) << 4));
#pragma unroll
            for (int p = 0; p < 2; ++p)
                ldsm4(bq[p], bBase + (b_r + p * 16) * 128 +
                                 (((ks2 + b_cb) ^ lr) << 4));
#pragma unroll
            for (int mt = 0; mt < 4; ++mt)
#pragma unroll
                for (int nt = 0; nt < 4; ++nt)
                    mma_f16(acc[mt][nt], afr[mt],
                            bq[nt >> 1][(nt & 1) * 2],
                            bq[nt >> 1][(nt & 1) * 2 + 1]);
        }
        // single-barrier ring: writes to s2 are post-barrier; its readers
        // finished pre-barrier -> no tail sync needed
        s  = (s  == 2) ? 0 : s  + 1;
        s2 = (s2 == 2) ? 0 : s2 + 1;
    }

    // epilogue: reference numerics f32( fp16(acc) +fp16 fp16(bias) )
#pragma unroll
    for (int mt = 0; mt < 4; ++mt) {
#pragma unroll
        for (int nt = 0; nt < 4; ++nt) {
            const int row = m0 + warp_m * 64 + mt * 16 + (lane >> 2);
            const int col = n0 + warp_n * 32 + nt * 8 + (lane & 3) * 2;
            const float2 bv = *reinterpret_cast<const float2*>(&bias[col]);
            const __half b0 = __float2half_rn(bv.x);
            const __half b1 = __float2half_rn(bv.y);
#pragma unroll
            for (int h = 0; h < 2; ++h) {
                const __half s0 = __hadd(__float2half(acc[mt][nt][2 * h + 0]), b0);
                const __half s1 = __hadd(__float2half(acc[mt][nt][2 * h + 1]), b1);
                float2 o;
                o.x = __half2float(s0);
                o.y = __half2float(s1);
                *reinterpret_cast<float2*>(
                    &Y[(size_t)(row + 8 * h) * Ndim + col]) = o;
            }
        }
    }
}

extern "C" void kernel_launch(void* const* d_in, const int* in_sizes, int n_in,
                              void* d_out, int out_size) {
    const float* x    = nullptr;
    const int*   wp   = nullptr;
    const float* bias = nullptr;
    for (int i = 0; i < n_in; ++i) {
        if (in_sizes[i] == Mdim * Kdim)      x    = (const float*)d_in[i];
        else if (in_sizes[i] == Ndim * KW)   wp   = (const int*)d_in[i];
        else if (in_sizes[i] == Ndim)        bias = (const float*)d_in[i];
    }
    float* y = (float*)d_out;

    cudaFuncSetAttribute(ternary_gemm_kernel,
                         cudaFuncAttributeMaxDynamicSharedMemorySize, SMEM_TOTAL);

    prepare_kernel<<<XCONV_BLOCKS + WDEC_BLOCKS, 256>>>(x, wp);
    dim3 grid(Ndim / BN, Mdim / BM);   // (64, 8) = 512 CTAs
    ternary_gemm_kernel<<<grid, NTHREADS, SMEM_TOTAL>>>(bias, y);
}